// round 14
// baseline (speedup 1.0000x reference)
#include <cuda_runtime.h>
#include <cuda_fp16.h>
#include <cstdint>

#define BATCH   16384
#define HID     512
#define NLAYERS 8
#define NOUT    16
#define WSCALE  4.4194173824159215e-04f  /* 0.01 / sqrt(512) */
#define BSCALE  0.01f
#define SLOPE   0.2f
#define GAIN    1.41421356237f
#define EPSV    1e-8f

// ---------------------------------------------------------------------------
// Scratch (allocation-free rule: __device__ globals)
// ---------------------------------------------------------------------------
__device__ __half g_A[2][(size_t)BATCH * HID];
__device__ __half g_W[(size_t)NLAYERS * HID * HID];

// ---------------------------------------------------------------------------
// Helpers
// ---------------------------------------------------------------------------
__device__ __forceinline__ uint32_t smem_u32(const void* p) {
    uint32_t a;
    asm("{ .reg .u64 t; cvta.to.shared.u64 t, %1; cvt.u32.u64 %0, t; }"
        : "=r"(a) : "l"(p));
    return a;
}
__device__ __forceinline__ void ldm_x4(uint32_t addr, uint32_t r[4]) {
    asm volatile(
        "ldmatrix.sync.aligned.m8n8.x4.shared.b16 {%0,%1,%2,%3}, [%4];"
        : "=r"(r[0]), "=r"(r[1]), "=r"(r[2]), "=r"(r[3]) : "r"(addr));
}
__device__ __forceinline__ void mma16816(float c[4], const uint32_t a[4],
                                         const uint32_t b[2]) {
    asm volatile(
        "mma.sync.aligned.m16n8k16.row.col.f32.f16.f16.f32 "
        "{%0,%1,%2,%3}, {%4,%5,%6,%7}, {%8,%9}, {%0,%1,%2,%3};"
        : "+f"(c[0]), "+f"(c[1]), "+f"(c[2]), "+f"(c[3])
        : "r"(a[0]), "r"(a[1]), "r"(a[2]), "r"(a[3]), "r"(b[0]), "r"(b[1]));
}
#define CP_ASYNC16(sa, ga) \
    asm volatile("cp.async.cg.shared.global [%0], [%1], 16;" :: "r"(sa), "l"(ga))
#define CP_COMMIT() asm volatile("cp.async.commit_group;")
#define CP_WAIT1() asm volatile("cp.async.wait_group 1;")
#define CP_WAIT0() asm volatile("cp.async.wait_group 0;")

// ---------------------------------------------------------------------------
// Weight conversion: w_eff = w * WSCALE -> fp16
// ---------------------------------------------------------------------------
__global__ void wconv_kernel(const float* __restrict__ w,
                             __half* __restrict__ wh) {
    size_t i = (size_t)blockIdx.x * blockDim.x + threadIdx.x;
    float4 v = ((const float4*)w)[i];
    union { uint2 u; __half h[4]; } ph;
    ph.h[0] = __float2half_rn(v.x * WSCALE);
    ph.h[1] = __float2half_rn(v.y * WSCALE);
    ph.h[2] = __float2half_rn(v.z * WSCALE);
    ph.h[3] = __float2half_rn(v.w * WSCALE);
    ((uint2*)wh)[i] = ph.u;
}

// ---------------------------------------------------------------------------
// Pixel norm -> fp16
// ---------------------------------------------------------------------------
__global__ void pixelnorm_kernel(const float* __restrict__ z,
                                 __half* __restrict__ a) {
    const int row = blockIdx.x;
    const int tid = threadIdx.x;
    float4 v = ((const float4*)(z + (size_t)row * HID))[tid];
    float s = v.x * v.x + v.y * v.y + v.z * v.z + v.w * v.w;
#pragma unroll
    for (int o = 16; o > 0; o >>= 1) s += __shfl_xor_sync(0xffffffffu, s, o);
    __shared__ float ws[4];
    if ((tid & 31) == 0) ws[tid >> 5] = s;
    __syncthreads();
    float tot = ws[0] + ws[1] + ws[2] + ws[3];
    float r = rsqrtf(tot * (1.0f / HID) + EPSV);
    union { uint2 u; __half h[4]; } ph;
    ph.h[0] = __float2half_rn(v.x * r);
    ph.h[1] = __float2half_rn(v.y * r);
    ph.h[2] = __float2half_rn(v.z * r);
    ph.h[3] = __float2half_rn(v.w * r);
    ((uint2*)a)[((size_t)row * HID) / 4 + tid] = ph.u;
}

// ---------------------------------------------------------------------------
// Single-term fp16 HMMA GEMM layer -- WARP-AUTONOMOUS pipeline.
// C[m,n] = sum_k a[m,k] * w_eff[n,k]
// Tile BM=128 x BN=128, 128 threads (2m x 2n warps), warp tile 64x64.
// Each warp owns a PRIVATE smem slice with the A-half + B-half it reads,
// loads it with its own cp.async, and synchronizes only with
// wait_group + __syncwarp -- NO __syncthreads in the mainloop, so warps
// drift out of phase and overlap each other's smem-port and tensor usage.
// Per-warp slice: 2-stage ring x (64x80 A + 64x80 B) = 20 KB; CTA 80 KB,
// 2 CTAs/SM = 160 KB.  Stride 80 B -> conflict-free ldmatrix.
// ---------------------------------------------------------------------------
#define RSTRIDE 80
#define HALF_BYTES (64 * RSTRIDE)        /* 5120: one 64-row half-plane */
#define WSTAGE_BYTES (2 * HALF_BYTES)    /* 10240: A half + B half */
#define WSLICE (2 * WSTAGE_BYTES)        /* 20480: 2-stage ring per warp */
#define SMEM_TOTAL (4 * WSLICE)          /* 81920 per CTA */
#define OFF_WA 0
#define OFF_WB HALF_BYTES
#define KSTAGES 16

// Load this warp's stage: A rows [arow0, arow0+64), B rows [brow0, brow0+64),
// k columns [kb, kb+32). 16 cp.async per lane total (8 A + 8 B).
__device__ __forceinline__ void load_warp_stage(uint32_t wbase,
                                                const __half* __restrict__ A,
                                                const __half* __restrict__ W,
                                                int arow0, int brow0, int kb,
                                                int lid) {
#pragma unroll
    for (int h = 0; h < 8; h++) {
        int u = lid + h * 32;           // 0..255
        int row = u >> 2, un = u & 3;
        CP_ASYNC16(wbase + OFF_WA + row * RSTRIDE + un * 16,
                   A + (size_t)(arow0 + row) * HID + kb + un * 8);
    }
#pragma unroll
    for (int h = 0; h < 8; h++) {
        int u = lid + h * 32;
        int row = u >> 2, un = u & 3;
        CP_ASYNC16(wbase + OFF_WB + row * RSTRIDE + un * 16,
                   W + (size_t)(brow0 + row) * HID + kb + un * 8);
    }
}

template <bool LAST>
__global__ __launch_bounds__(128, 2) void gemm_layer(
    const __half* __restrict__ A, const __half* __restrict__ W,
    const float* __restrict__ bias, __half* __restrict__ O,
    float* __restrict__ OutF) {
    extern __shared__ char smem[];
    const int tid = threadIdx.x;
    const int wid = tid >> 5;
    const int lid = tid & 31;
    const int wm = wid >> 1;            // 0..1 -> 64 rows each
    const int wn = wid & 1;             // 0..1 -> 64 cols each
    const int bm = blockIdx.y * 128;
    const int bn = blockIdx.x * 128;
    const uint32_t wb = smem_u32(smem) + wid * WSLICE;   // this warp's slice

    const int arow0 = bm + wm * 64;
    const int brow0 = bn + wn * 64;

    const int lt = lid >> 3;            // ldmatrix tile index 0..3
    const int li = lid & 7;

    // Slice-relative LDSM offsets (rows are LOCAL to the 64-row half):
    uint32_t aoff[4], boff[4];
#pragma unroll
    for (int mf = 0; mf < 4; mf++)
        aoff[mf] = OFF_WA + ((lt & 1) * 8 + li + mf * 16) * RSTRIDE +
                   (lt >> 1) * 16;
#pragma unroll
    for (int p = 0; p < 4; p++)
        boff[p] = OFF_WB + ((lt >> 1) * 8 + li + p * 16) * RSTRIDE +
                  (lt & 1) * 16;

    float acc[4][8][4];
#pragma unroll
    for (int a = 0; a < 4; a++)
#pragma unroll
        for (int b = 0; b < 8; b++)
#pragma unroll
            for (int c = 0; c < 4; c++) acc[a][b][c] = 0.0f;

    // prologue: stage 0 into ring buffer 0 (this warp only)
    load_warp_stage(wb, A, W, arow0, brow0, 0, lid);
    CP_COMMIT();

    for (int s = 0; s < KSTAGES; s++) {
        if (s + 1 < KSTAGES) {
            // buffer (s+1)&1 held stage s-1, which THIS warp finished
            // computing before issuing these copies (program order) -> no
            // WAR hazard, no block barrier needed.
            load_warp_stage(wb + ((s + 1) & 1) * WSTAGE_BYTES, A, W, arow0,
                            brow0, (s + 1) * 32, lid);
            CP_COMMIT();
            CP_WAIT1();
        } else {
            CP_WAIT0();
        }
        __syncwarp();   // publish all lanes' completed cp.async warp-wide

        uint32_t sc = wb + (s & 1) * WSTAGE_BYTES;
#pragma unroll
        for (int kk = 0; kk < 2; kk++) {
            uint32_t ah[4][4];
#pragma unroll
            for (int mf = 0; mf < 4; mf++)
                ldm_x4(sc + aoff[mf] + kk * 32, ah[mf]);
            uint32_t bh[8][2];
#pragma unroll
            for (int p = 0; p < 4; p++) {
                uint32_t r[4];
                ldm_x4(sc + boff[p] + kk * 32, r);
                bh[2 * p][0] = r[0]; bh[2 * p][1] = r[1];
                bh[2 * p + 1][0] = r[2]; bh[2 * p + 1][1] = r[3];
            }
#pragma unroll
            for (int mf = 0; mf < 4; mf++)
#pragma unroll
                for (int nf = 0; nf < 8; nf++)
                    mma16816(acc[mf][nf], ah[mf], bh[nf]);
        }
        __syncwarp();   // all lanes done reading before next overwrite
    }

    // Epilogue: m16n8 c mapping: reg e -> row=(l/4)+(e>=2?8:0), col=(l%4)*2+(e&1)
    float bj[8][2];
#pragma unroll
    for (int nf = 0; nf < 8; nf++) {
        int col = brow0 + nf * 8 + (lid & 3) * 2;
        bj[nf][0] = bias[col] * BSCALE;
        bj[nf][1] = bias[col + 1] * BSCALE;
    }

#pragma unroll
    for (int mf = 0; mf < 4; mf++) {
#pragma unroll
        for (int half_ : {0, 1}) {
            int row = arow0 + mf * 16 + (lid >> 2) + half_ * 8;
#pragma unroll
            for (int nf = 0; nf < 8; nf++) {
                int col = brow0 + nf * 8 + (lid & 3) * 2;
                float x0 = acc[mf][nf][half_ * 2 + 0] + bj[nf][0];
                float x1 = acc[mf][nf][half_ * 2 + 1] + bj[nf][1];
                x0 = (x0 > 0.0f ? x0 : SLOPE * x0) * GAIN;
                x1 = (x1 > 0.0f ? x1 : SLOPE * x1) * GAIN;
                if (!LAST) {
                    size_t off = (size_t)row * HID + col;
                    *(__half2*)(O + off) =
                        __halves2half2(__float2half_rn(x0), __float2half_rn(x1));
                } else {
                    float2 p = make_float2(x0, x1);
#pragma unroll
                    for (int r = 0; r < NOUT; r++) {
                        size_t off = ((size_t)row * NOUT + r) * HID + col;
                        *(float2*)(OutF + off) = p;
                    }
                }
            }
        }
    }
}

// ---------------------------------------------------------------------------
extern "C" void kernel_launch(void* const* d_in, const int* in_sizes, int n_in,
                              void* d_out, int out_size) {
    const float* z = (const float*)d_in[0];
    const float* weight = (const float*)d_in[1];
    const float* bias = (const float*)d_in[2];
    float* out = (float*)d_out;

    __half *a, *w;
    cudaGetSymbolAddress((void**)&a, g_A);
    cudaGetSymbolAddress((void**)&w, g_W);

    cudaFuncSetAttribute(gemm_layer<false>,
                         cudaFuncAttributeMaxDynamicSharedMemorySize, SMEM_TOTAL);
    cudaFuncSetAttribute(gemm_layer<true>,
                         cudaFuncAttributeMaxDynamicSharedMemorySize, SMEM_TOTAL);

    wconv_kernel<<<2048, 256>>>(weight, w);
    pixelnorm_kernel<<<BATCH, 128>>>(z, a);

    const size_t ABUF = (size_t)BATCH * HID;
    const size_t WBUF = (size_t)HID * HID;
    dim3 grid(HID / 128, BATCH / 128);  // (4, 128) = 512 CTAs
    for (int l = 0; l < NLAYERS; l++) {
        const __half* Ain = a + (l & 1) * ABUF;
        __half* Aout = a + ((l + 1) & 1) * ABUF;
        const __half* Wl = w + (size_t)l * WBUF;
        const float* bl = bias + (size_t)l * HID;
        if (l == NLAYERS - 1)
            gemm_layer<true><<<grid, 128, SMEM_TOTAL>>>(Ain, Wl, bl, nullptr,
                                                        out);
        else
            gemm_layer<false><<<grid, 128, SMEM_TOTAL>>>(Ain, Wl, bl, Aout,
                                                         nullptr);
    }
}

// round 16
// speedup vs baseline: 1.1690x; 1.1690x over previous
#include <cuda_runtime.h>
#include <cuda_fp16.h>
#include <cstdint>

#define BATCH   16384
#define HID     512
#define NLAYERS 8
#define NOUT    16
#define WSCALE  4.4194173824159215e-04f  /* 0.01 / sqrt(512) */
#define BSCALE  0.01f
#define SLOPE   0.2f
#define GAIN    1.41421356237f
#define EPSV    1e-8f

// ---------------------------------------------------------------------------
// Scratch (allocation-free rule: __device__ globals)
// ---------------------------------------------------------------------------
__device__ __half g_A[2][(size_t)BATCH * HID];
__device__ __half g_W[(size_t)NLAYERS * HID * HID];

// ---------------------------------------------------------------------------
// Helpers
// ---------------------------------------------------------------------------
__device__ __forceinline__ uint32_t smem_u32(const void* p) {
    uint32_t a;
    asm("{ .reg .u64 t; cvta.to.shared.u64 t, %1; cvt.u32.u64 %0, t; }"
        : "=r"(a) : "l"(p));
    return a;
}
__device__ __forceinline__ void ldm_x4(uint32_t addr, uint32_t r[4]) {
    asm volatile(
        "ldmatrix.sync.aligned.m8n8.x4.shared.b16 {%0,%1,%2,%3}, [%4];"
        : "=r"(r[0]), "=r"(r[1]), "=r"(r[2]), "=r"(r[3]) : "r"(addr));
}
__device__ __forceinline__ void mma16816(float c[4], const uint32_t a[4],
                                         const uint32_t b[2]) {
    asm volatile(
        "mma.sync.aligned.m16n8k16.row.col.f32.f16.f16.f32 "
        "{%0,%1,%2,%3}, {%4,%5,%6,%7}, {%8,%9}, {%0,%1,%2,%3};"
        : "+f"(c[0]), "+f"(c[1]), "+f"(c[2]), "+f"(c[3])
        : "r"(a[0]), "r"(a[1]), "r"(a[2]), "r"(a[3]), "r"(b[0]), "r"(b[1]));
}
#define CP_ASYNC16(sa, ga) \
    asm volatile("cp.async.cg.shared.global [%0], [%1], 16;" :: "r"(sa), "l"(ga))
#define CP_COMMIT() asm volatile("cp.async.commit_group;")
#define CP_WAIT1() asm volatile("cp.async.wait_group 1;")
#define CP_WAIT0() asm volatile("cp.async.wait_group 0;")

// ---------------------------------------------------------------------------
// Weight conversion: w_eff = w * WSCALE -> fp16
// ---------------------------------------------------------------------------
__global__ void wconv_kernel(const float* __restrict__ w,
                             __half* __restrict__ wh) {
    size_t i = (size_t)blockIdx.x * blockDim.x + threadIdx.x;
    float4 v = ((const float4*)w)[i];
    union { uint2 u; __half h[4]; } ph;
    ph.h[0] = __float2half_rn(v.x * WSCALE);
    ph.h[1] = __float2half_rn(v.y * WSCALE);
    ph.h[2] = __float2half_rn(v.z * WSCALE);
    ph.h[3] = __float2half_rn(v.w * WSCALE);
    ((uint2*)wh)[i] = ph.u;
}

// ---------------------------------------------------------------------------
// Pixel norm -> fp16
// ---------------------------------------------------------------------------
__global__ void pixelnorm_kernel(const float* __restrict__ z,
                                 __half* __restrict__ a) {
    const int row = blockIdx.x;
    const int tid = threadIdx.x;
    float4 v = ((const float4*)(z + (size_t)row * HID))[tid];
    float s = v.x * v.x + v.y * v.y + v.z * v.z + v.w * v.w;
#pragma unroll
    for (int o = 16; o > 0; o >>= 1) s += __shfl_xor_sync(0xffffffffu, s, o);
    __shared__ float ws[4];
    if ((tid & 31) == 0) ws[tid >> 5] = s;
    __syncthreads();
    float tot = ws[0] + ws[1] + ws[2] + ws[3];
    float r = rsqrtf(tot * (1.0f / HID) + EPSV);
    union { uint2 u; __half h[4]; } ph;
    ph.h[0] = __float2half_rn(v.x * r);
    ph.h[1] = __float2half_rn(v.y * r);
    ph.h[2] = __float2half_rn(v.z * r);
    ph.h[3] = __float2half_rn(v.w * r);
    ((uint2*)a)[((size_t)row * HID) / 4 + tid] = ph.u;
}

// ---------------------------------------------------------------------------
// Single-term fp16 HMMA GEMM layer.  C[m,n] = sum_k a[m,k] * w_eff[n,k]
// Tile BM=128 x BN=128, BK=64 (8 stages -> HALF the barriers of R13),
// 128 threads (2m x 2n warps), warp tile 64x64 (128 LDSM-bytes/MMA),
// 3-stage cp.async ring with the validated single-barrier ordering
// (wait -> sync -> issue(s+2) -> compute(s)), 2 CTAs/SM.
// SMEM rows: 64 half = 128 B data, stride 144 B (9x16; lane addresses step
// 4 banks/row mod 32 -> conflict-free ldmatrix).
// ---------------------------------------------------------------------------
#define RSTRIDE 144
#define PLANE_BYTES (128 * RSTRIDE)      /* 18432 */
#define STAGE_BYTES (2 * PLANE_BYTES)    /* 36864 */
#define NSTAGE 3
#define SMEM_TOTAL (NSTAGE * STAGE_BYTES) /* 110592; x2 CTAs = 221184 */
#define OFF_A 0
#define OFF_B PLANE_BYTES
#define KSTAGES 8                         /* 512 / 64 */

__device__ __forceinline__ void load_stage(uint32_t sp,
                                           const __half* __restrict__ A,
                                           const __half* __restrict__ W,
                                           int bm, int bn, int kb, int tid) {
    // A plane: 128 rows x 8 units = 1024 cp.async (8/thread)
#pragma unroll
    for (int h = 0; h < 8; h++) {
        int u = tid + h * 128;
        int row = u >> 3, un = u & 7;
        CP_ASYNC16(sp + OFF_A + row * RSTRIDE + un * 16,
                   A + (size_t)(bm + row) * HID + kb + un * 8);
    }
    // B plane: 128 rows x 8 units = 1024 cp.async (8/thread)
#pragma unroll
    for (int h = 0; h < 8; h++) {
        int u = tid + h * 128;
        int row = u >> 3, un = u & 7;
        CP_ASYNC16(sp + OFF_B + row * RSTRIDE + un * 16,
                   W + (size_t)(bn + row) * HID + kb + un * 8);
    }
}

template <bool LAST>
__global__ __launch_bounds__(128, 2) void gemm_layer(
    const __half* __restrict__ A, const __half* __restrict__ W,
    const float* __restrict__ bias, __half* __restrict__ O,
    float* __restrict__ OutF) {
    extern __shared__ char smem[];
    const uint32_t sb = smem_u32(smem);
    const int tid = threadIdx.x;
    const int wid = tid >> 5;
    const int lid = tid & 31;
    const int wm = wid >> 1;            // 0..1 -> 64 rows each
    const int wn = wid & 1;             // 0..1 -> 64 cols each
    const int bm = blockIdx.y * 128;
    const int bn = blockIdx.x * 128;

    const int lt = lid >> 3;            // ldmatrix tile index 0..3
    const int li = lid & 7;

    const int am_row = wm * 64 + (lt & 1) * 8 + li;
    const int bn_row0 = wn * 64 + (lt >> 1) * 8 + li;
    uint32_t aoff[4], boff[4];
#pragma unroll
    for (int mf = 0; mf < 4; mf++)
        aoff[mf] = OFF_A + (am_row + mf * 16) * RSTRIDE + (lt >> 1) * 16;
#pragma unroll
    for (int p = 0; p < 4; p++)
        boff[p] = OFF_B + (bn_row0 + p * 16) * RSTRIDE + (lt & 1) * 16;

    float acc[4][8][4];
#pragma unroll
    for (int a = 0; a < 4; a++)
#pragma unroll
        for (int b = 0; b < 8; b++)
#pragma unroll
            for (int c = 0; c < 4; c++) acc[a][b][c] = 0.0f;

    // prologue: stages 0,1 into ring buffers 0,1
#pragma unroll
    for (int s = 0; s < 2; s++) {
        load_stage(sb + s * STAGE_BYTES, A, W, bm, bn, s * 64, tid);
        CP_COMMIT();
    }

    uint32_t sc = sb;                        // compute buffer (stage s)
    uint32_t sp = sb + 2 * STAGE_BYTES;      // prefetch buffer (stage s+2)

    for (int s = 0; s < KSTAGES; s++) {
        // Validated single-barrier ordering: own-wait (stage-s groups done)
        // -> barrier (publishes all threads' stage-s data AND orders
        // compute(s-1) before buffer (s+2)%3==(s-1)%3 reuse) -> issue
        // loads(s+2) -> compute(s).
        if (s < KSTAGES - 1) CP_WAIT1();
        else CP_WAIT0();
        __syncthreads();
        if (s + 2 < KSTAGES) {
            load_stage(sp, A, W, bm, bn, (s + 2) * 64, tid);
            CP_COMMIT();
        }

#pragma unroll
        for (int kk = 0; kk < 4; kk++) {
            uint32_t ah[4][4];
#pragma unroll
            for (int mf = 0; mf < 4; mf++)
                ldm_x4(sc + aoff[mf] + kk * 32, ah[mf]);
            uint32_t bh[8][2];
#pragma unroll
            for (int p = 0; p < 4; p++) {
                uint32_t r[4];
                ldm_x4(sc + boff[p] + kk * 32, r);
                bh[2 * p][0] = r[0]; bh[2 * p][1] = r[1];
                bh[2 * p + 1][0] = r[2]; bh[2 * p + 1][1] = r[3];
            }
#pragma unroll
            for (int mf = 0; mf < 4; mf++)
#pragma unroll
                for (int nf = 0; nf < 8; nf++)
                    mma16816(acc[mf][nf], ah[mf], bh[nf]);
        }
        // rotate ring pointers
        sc += STAGE_BYTES;
        if (sc == sb + NSTAGE * STAGE_BYTES) sc = sb;
        sp += STAGE_BYTES;
        if (sp == sb + NSTAGE * STAGE_BYTES) sp = sb;
    }

    // Epilogue: m16n8 c mapping: reg e -> row=(l/4)+(e>=2?8:0), col=(l%4)*2+(e&1)
    float bj[8][2];
#pragma unroll
    for (int nf = 0; nf < 8; nf++) {
        int col = bn + wn * 64 + nf * 8 + (lid & 3) * 2;
        bj[nf][0] = bias[col] * BSCALE;
        bj[nf][1] = bias[col + 1] * BSCALE;
    }

#pragma unroll
    for (int mf = 0; mf < 4; mf++) {
#pragma unroll
        for (int half_ : {0, 1}) {
            int row = bm + wm * 64 + mf * 16 + (lid >> 2) + half_ * 8;
#pragma unroll
            for (int nf = 0; nf < 8; nf++) {
                int col = bn + wn * 64 + nf * 8 + (lid & 3) * 2;
                float x0 = acc[mf][nf][half_ * 2 + 0] + bj[nf][0];
                float x1 = acc[mf][nf][half_ * 2 + 1] + bj[nf][1];
                x0 = (x0 > 0.0f ? x0 : SLOPE * x0) * GAIN;
                x1 = (x1 > 0.0f ? x1 : SLOPE * x1) * GAIN;
                if (!LAST) {
                    size_t off = (size_t)row * HID + col;
                    *(__half2*)(O + off) =
                        __halves2half2(__float2half_rn(x0), __float2half_rn(x1));
                } else {
                    float2 p = make_float2(x0, x1);
#pragma unroll
                    for (int r = 0; r < NOUT; r++) {
                        size_t off = ((size_t)row * NOUT + r) * HID + col;
                        *(float2*)(OutF + off) = p;
                    }
                }
            }
        }
    }
}

// ---------------------------------------------------------------------------
extern "C" void kernel_launch(void* const* d_in, const int* in_sizes, int n_in,
                              void* d_out, int out_size) {
    const float* z = (const float*)d_in[0];
    const float* weight = (const float*)d_in[1];
    const float* bias = (const float*)d_in[2];
    float* out = (float*)d_out;

    __half *a, *w;
    cudaGetSymbolAddress((void**)&a, g_A);
    cudaGetSymbolAddress((void**)&w, g_W);

    cudaFuncSetAttribute(gemm_layer<false>,
                         cudaFuncAttributeMaxDynamicSharedMemorySize, SMEM_TOTAL);
    cudaFuncSetAttribute(gemm_layer<true>,
                         cudaFuncAttributeMaxDynamicSharedMemorySize, SMEM_TOTAL);

    wconv_kernel<<<2048, 256>>>(weight, w);
    pixelnorm_kernel<<<BATCH, 128>>>(z, a);

    const size_t ABUF = (size_t)BATCH * HID;
    const size_t WBUF = (size_t)HID * HID;
    dim3 grid(HID / 128, BATCH / 128);  // (4, 128) = 512 CTAs
    for (int l = 0; l < NLAYERS; l++) {
        const __half* Ain = a + (l & 1) * ABUF;
        __half* Aout = a + ((l + 1) & 1) * ABUF;
        const __half* Wl = w + (size_t)l * WBUF;
        const float* bl = bias + (size_t)l * HID;
        if (l == NLAYERS - 1)
            gemm_layer<true><<<grid, 128, SMEM_TOTAL>>>(Ain, Wl, bl, nullptr,
                                                        out);
        else
            gemm_layer<false><<<grid, 128, SMEM_TOTAL>>>(Ain, Wl, bl, Aout,
                                                         nullptr);
    }
}